// round 5
// baseline (speedup 1.0000x reference)
#include <cuda_runtime.h>
#include <cuda_fp16.h>

// MeshGCN 2-layer GCN, N=100000, FEAT=16, E=3.2M.
// out_l[d] = dinv[d] * ( hs_l[d] + sum_{(s,d) in E} hs_l[s] ) + b_l
//   hs_l = (in_l @ W_l) * dinv,  dinv = rsqrt(deg_in + 1)
// Fixed-stride bucket adjacency (96 slots/node) built in ONE kernel that also
// produces degrees (no scan, no separate histogram). hs stored packed fp16
// (32B/node); fp32 accumulation; warp-per-node atomic-free aggregation.
// Overflow (prob ~1e-20 but handled for correctness) goes to a spill list
// processed by a tiny atomic kernel per layer.

#define NMAX 100000
#define F 16
#define SLOTS 96
#define SPILLMAX 8192

__device__ int    g_cnt[NMAX];
__device__ int    g_adj[NMAX * SLOTS];
__device__ int    g_spill_cnt;
__device__ int    g_spill[SPILLMAX * 2];
__device__ float  g_dinv[NMAX];
__device__ __align__(16) uint4  g_hsh[NMAX * 2];   // fp16x2 packed, 32B/node
__device__ float4 g_agg[NMAX * 4];

__device__ __forceinline__ unsigned pack2(float a, float b) {
    __half2 h = __floats2half2_rn(a, b);
    return reinterpret_cast<unsigned&>(h);
}
__device__ __forceinline__ void acc8(uint4 v, float* a) {
    __half2 h; float2 f;
    h = reinterpret_cast<__half2&>(v.x); f = __half22float2(h); a[0] += f.x; a[1] += f.y;
    h = reinterpret_cast<__half2&>(v.y); f = __half22float2(h); a[2] += f.x; a[3] += f.y;
    h = reinterpret_cast<__half2&>(v.z); f = __half22float2(h); a[4] += f.x; a[5] += f.y;
    h = reinterpret_cast<__half2&>(v.w); f = __half22float2(h); a[6] += f.x; a[7] += f.y;
}

// ---------------- zero counters ----------------
__global__ __launch_bounds__(256) void k_init(int n) {
    int i = blockIdx.x * 256 + threadIdx.x;
    if (i < n) g_cnt[i] = 0;
    if (i == 0) g_spill_cnt = 0;
}

// ---------------- one-pass bucket build: degree + placement ----------------
__global__ __launch_bounds__(256) void k_bucket(const int* __restrict__ src,
                                                const int* __restrict__ dst, int E) {
    int e = blockIdx.x * 256 + threadIdx.x;
    if (e >= E) return;
    int s = src[e];
    int d = dst[e];
    int pos = atomicAdd(&g_cnt[d], 1);
    if (pos < SLOTS) {
        g_adj[(size_t)d * SLOTS + pos] = s;
    } else {
        int sp = atomicAdd(&g_spill_cnt, 1);
        if (sp < SPILLMAX) { g_spill[2 * sp] = s; g_spill[2 * sp + 1] = d; }
    }
}

// ---------------- dense: hs = (x @ W1) * dinv (fp16 packed) ----------------
__global__ __launch_bounds__(256) void k_pre1(const float* __restrict__ x,
                                              const float* __restrict__ W, int n) {
    __shared__ float sW[256];
    int tid = threadIdx.x;
    sW[tid] = W[tid];
    __syncthreads();
    int i = blockIdx.x * 256 + tid;
    if (i >= n) return;

    const float4* xp = reinterpret_cast<const float4*>(x) + (size_t)i * 4;
    float xr[16];
#pragma unroll
    for (int c = 0; c < 4; c++) {
        float4 t = xp[c];
        xr[c * 4 + 0] = t.x; xr[c * 4 + 1] = t.y;
        xr[c * 4 + 2] = t.z; xr[c * 4 + 3] = t.w;
    }
    float acc[16];
#pragma unroll
    for (int j = 0; j < 16; j++) acc[j] = 0.0f;
#pragma unroll
    for (int k = 0; k < 16; k++) {
        float xk = xr[k];
#pragma unroll
        for (int j = 0; j < 16; j++) acc[j] += xk * sW[k * 16 + j];
    }
    float dv = rsqrtf((float)(g_cnt[i] + 1));
    g_dinv[i] = dv;
#pragma unroll
    for (int j = 0; j < 16; j++) acc[j] *= dv;
    g_hsh[(size_t)i * 2 + 0] = make_uint4(pack2(acc[0], acc[1]),   pack2(acc[2], acc[3]),
                                          pack2(acc[4], acc[5]),   pack2(acc[6], acc[7]));
    g_hsh[(size_t)i * 2 + 1] = make_uint4(pack2(acc[8], acc[9]),   pack2(acc[10], acc[11]),
                                          pack2(acc[12], acc[13]), pack2(acc[14], acc[15]));
}

// ---------------- bucket aggregation: warp/node, 2 lanes/edge, fp32 accum ----
// agg[node] = hs[node] + sum_{s in bucket row} hs[s]
__global__ __launch_bounds__(256) void k_agg(int n) {
    int lane = threadIdx.x & 31;
    int node = blockIdx.x * 8 + (threadIdx.x >> 5);
    if (node >= n) return;
    int c = lane & 1;        // which 16B half of the 32B node record
    int g = lane >> 1;       // neighbor slot within chunk (0..15)

    int len = g_cnt[node];
    if (len > SLOTS) len = SLOTS;
    const int* row = &g_adj[(size_t)node * SLOTS];

    float acc[8];
#pragma unroll
    for (int j = 0; j < 8; j++) acc[j] = 0.0f;
    if (g == 0) {            // self-loop seed
        uint4 v = g_hsh[(size_t)node * 2 + c];
        acc8(v, acc);
    }

    for (int base = 0; base < len; base += 32) {
        int sidx = (base + lane < len) ? __ldg(&row[base + lane]) : 0;
        int nch = len - base; if (nch > 32) nch = 32;
        int iters = (nch + 15) >> 4;
#pragma unroll 2
        for (int it = 0; it < iters; it++) {
            int idx = it * 16 + g;
            int s = __shfl_sync(0xffffffffu, sidx, idx & 31);
            if (idx < nch) {
                uint4 v = __ldg(&g_hsh[(size_t)s * 2 + c]);
                acc8(v, acc);
            }
        }
    }
    // reduce across the 16 neighbor slots (lanes with equal c: xor bits 1..4)
#pragma unroll
    for (int off = 2; off <= 16; off <<= 1) {
#pragma unroll
        for (int j = 0; j < 8; j++)
            acc[j] += __shfl_xor_sync(0xffffffffu, acc[j], off);
    }
    if (g == 0) {
        g_agg[(size_t)node * 4 + c * 2 + 0] = make_float4(acc[0], acc[1], acc[2], acc[3]);
        g_agg[(size_t)node * 4 + c * 2 + 1] = make_float4(acc[4], acc[5], acc[6], acc[7]);
    }
}

// ---------------- spill cleanup (normally 0 iterations) ----------------
__global__ __launch_bounds__(256) void k_spill() {
    int m = g_spill_cnt;
    if (m > SPILLMAX) m = SPILLMAX;
    for (int i = threadIdx.x; i < m; i += 256) {
        int s = g_spill[2 * i];
        int d = g_spill[2 * i + 1];
        float a[16];
#pragma unroll
        for (int j = 0; j < 16; j++) a[j] = 0.0f;
        acc8(g_hsh[(size_t)s * 2 + 0], a);
        acc8(g_hsh[(size_t)s * 2 + 1], a + 8);
        float* ap = reinterpret_cast<float*>(&g_agg[(size_t)d * 4]);
#pragma unroll
        for (int c = 0; c < 4; c++) {
            asm volatile("red.global.add.v4.f32 [%0], {%1, %2, %3, %4};"
                         :: "l"(ap + c * 4), "f"(a[c * 4 + 0]), "f"(a[c * 4 + 1]),
                            "f"(a[c * 4 + 2]), "f"(a[c * 4 + 3])
                         : "memory");
        }
    }
}

// ---------------- y = relu(dinv*agg + b1) ; hs = (y @ W2) * dinv (fp16) ------
__global__ __launch_bounds__(256) void k_mid(const float* __restrict__ W2,
                                             const float* __restrict__ b1, int n) {
    __shared__ float sW[256];
    __shared__ float sb[16];
    int tid = threadIdx.x;
    sW[tid] = W2[tid];
    if (tid < 16) sb[tid] = b1[tid];
    __syncthreads();
    int i = blockIdx.x * 256 + tid;
    if (i >= n) return;

    float dv = g_dinv[i];
    float y[16];
#pragma unroll
    for (int c = 0; c < 4; c++) {
        float4 a = g_agg[(size_t)i * 4 + c];
        float v0 = a.x * dv + sb[c * 4 + 0];
        float v1 = a.y * dv + sb[c * 4 + 1];
        float v2 = a.z * dv + sb[c * 4 + 2];
        float v3 = a.w * dv + sb[c * 4 + 3];
        y[c * 4 + 0] = v0 > 0.0f ? v0 : 0.0f;
        y[c * 4 + 1] = v1 > 0.0f ? v1 : 0.0f;
        y[c * 4 + 2] = v2 > 0.0f ? v2 : 0.0f;
        y[c * 4 + 3] = v3 > 0.0f ? v3 : 0.0f;
    }
    float acc[16];
#pragma unroll
    for (int j = 0; j < 16; j++) acc[j] = 0.0f;
#pragma unroll
    for (int k = 0; k < 16; k++) {
        float yk = y[k];
#pragma unroll
        for (int j = 0; j < 16; j++) acc[j] += yk * sW[k * 16 + j];
    }
#pragma unroll
    for (int j = 0; j < 16; j++) acc[j] *= dv;
    g_hsh[(size_t)i * 2 + 0] = make_uint4(pack2(acc[0], acc[1]),   pack2(acc[2], acc[3]),
                                          pack2(acc[4], acc[5]),   pack2(acc[6], acc[7]));
    g_hsh[(size_t)i * 2 + 1] = make_uint4(pack2(acc[8], acc[9]),   pack2(acc[10], acc[11]),
                                          pack2(acc[12], acc[13]), pack2(acc[14], acc[15]));
}

// ---------------- out = dinv*agg + b2 ----------------
__global__ __launch_bounds__(256) void k_final(const float* __restrict__ b2,
                                               float* __restrict__ out, int n) {
    __shared__ float sb[16];
    int tid = threadIdx.x;
    if (tid < 16) sb[tid] = b2[tid];
    __syncthreads();
    int i = blockIdx.x * 256 + tid;
    if (i >= n) return;

    float dv = g_dinv[i];
    float4* op = reinterpret_cast<float4*>(out) + (size_t)i * 4;
#pragma unroll
    for (int c = 0; c < 4; c++) {
        float4 a = g_agg[(size_t)i * 4 + c];
        float4 o;
        o.x = a.x * dv + sb[c * 4 + 0];
        o.y = a.y * dv + sb[c * 4 + 1];
        o.z = a.z * dv + sb[c * 4 + 2];
        o.w = a.w * dv + sb[c * 4 + 3];
        op[c] = o;
    }
}

extern "C" void kernel_launch(void* const* d_in, const int* in_sizes, int n_in,
                              void* d_out, int out_size) {
    const float* x  = (const float*)d_in[0];
    const int*   ei = (const int*)  d_in[1];
    const float* W1 = (const float*)d_in[2];
    const float* b1 = (const float*)d_in[3];
    const float* W2 = (const float*)d_in[4];
    const float* b2 = (const float*)d_in[5];
    float* out = (float*)d_out;

    int E = in_sizes[1] / 2;
    int n = in_sizes[0] / F;
    const int* src = ei;
    const int* dst = ei + E;

    int nb_n = (n + 255) / 256;
    int nb_e = (E + 255) / 256;
    int nb_w = (n + 7) / 8;

    k_init   <<<nb_n, 256>>>(n);
    k_bucket <<<nb_e, 256>>>(src, dst, E);
    k_pre1   <<<nb_n, 256>>>(x, W1, n);
    k_agg    <<<nb_w, 256>>>(n);
    k_spill  <<<1,    256>>>();
    k_mid    <<<nb_n, 256>>>(W2, b1, n);
    k_agg    <<<nb_w, 256>>>(n);
    k_spill  <<<1,    256>>>();
    k_final  <<<nb_n, 256>>>(b2, out, n);
}

// round 6
// speedup vs baseline: 1.0556x; 1.0556x over previous
#include <cuda_runtime.h>

// MeshGCN 2-layer GCN, N=100000, FEAT=16, E=3.2M.
// out_l[d] = dinv[d] * ( hs_l[d] + sum_{(s,d) in E} hs_l[s] ) + b_l
//   hs_l = (in_l @ W_l) * dinv,  dinv = rsqrt(deg_in + 1)
// Fixed-stride bucket adjacency (96 slots/node), built in one kernel that also
// yields degrees. Aggregation: 4 lanes per node, each lane owns one float4
// feature column and serially accumulates all neighbors -> NO reduction tail,
// ~1 warp-instruction per edge. fp32 throughout. Spill (prob ~1e-13) handled
// inside k_agg's tail.

#define NMAX 100000
#define F 16
#define SLOTS 96
#define SPILLMAX 8192

__device__ int    g_cnt[NMAX];
__device__ int    g_adj[NMAX * SLOTS];
__device__ int    g_spill_cnt;
__device__ int    g_spill[SPILLMAX * 2];
__device__ float  g_dinv[NMAX];
__device__ float4 g_hs [NMAX * 4];
__device__ float4 g_agg[NMAX * 4];

// ---------------- zero counters ----------------
__global__ __launch_bounds__(256) void k_init(int n) {
    int i = blockIdx.x * 256 + threadIdx.x;
    if (i < n) g_cnt[i] = 0;
    if (i == 0) g_spill_cnt = 0;
}

// ---------------- one-pass bucket build: degree + placement ----------------
__global__ __launch_bounds__(256) void k_bucket(const int* __restrict__ src,
                                                const int* __restrict__ dst, int E) {
    int e = blockIdx.x * 256 + threadIdx.x;
    if (e >= E) return;
    int s = src[e];
    int d = dst[e];
    int pos = atomicAdd(&g_cnt[d], 1);
    if (pos < SLOTS) {
        g_adj[(size_t)d * SLOTS + pos] = s;
    } else {
        int sp = atomicAdd(&g_spill_cnt, 1);
        if (sp < SPILLMAX) { g_spill[2 * sp] = s; g_spill[2 * sp + 1] = d; }
    }
}

// ---------------- dense: hs = (x @ W1) * dinv ----------------
__global__ __launch_bounds__(256) void k_pre1(const float* __restrict__ x,
                                              const float* __restrict__ W, int n) {
    __shared__ float sW[256];
    int tid = threadIdx.x;
    sW[tid] = W[tid];
    __syncthreads();
    int i = blockIdx.x * 256 + tid;
    if (i >= n) return;

    const float4* xp = reinterpret_cast<const float4*>(x) + (size_t)i * 4;
    float xr[16];
#pragma unroll
    for (int c = 0; c < 4; c++) {
        float4 t = xp[c];
        xr[c * 4 + 0] = t.x; xr[c * 4 + 1] = t.y;
        xr[c * 4 + 2] = t.z; xr[c * 4 + 3] = t.w;
    }
    float acc[16];
#pragma unroll
    for (int j = 0; j < 16; j++) acc[j] = 0.0f;
#pragma unroll
    for (int k = 0; k < 16; k++) {
        float xk = xr[k];
#pragma unroll
        for (int j = 0; j < 16; j++) acc[j] += xk * sW[k * 16 + j];
    }
    float dv = rsqrtf((float)(g_cnt[i] + 1));
    g_dinv[i] = dv;
#pragma unroll
    for (int c = 0; c < 4; c++) {
        float4 o;
        o.x = acc[c * 4 + 0] * dv; o.y = acc[c * 4 + 1] * dv;
        o.z = acc[c * 4 + 2] * dv; o.w = acc[c * 4 + 3] * dv;
        g_hs[(size_t)i * 4 + c] = o;
    }
}

// ---------------- aggregation: 4 lanes per node, serial, no reduce ----------
// agg[node] = hs[node] + sum_{s in bucket row} hs[s]
__global__ __launch_bounds__(256) void k_agg(int n) {
    int lane  = threadIdx.x & 31;
    int c     = lane & 3;                       // feature column (float4 slot)
    int qbase = lane & ~3;                      // first lane of this quad
    int node  = blockIdx.x * 64 + ((threadIdx.x >> 2));  // 64 nodes per block
    if (node >= n) return;

    int raw = g_cnt[node];
    int len = raw < SLOTS ? raw : SLOTS;
    const int* row = &g_adj[(size_t)node * SLOTS];

    float4 acc = g_hs[(size_t)node * 4 + c];    // self-loop seed

    int j = 0;
    for (; j + 4 <= len; j += 4) {
        int a = __ldg(&row[j + c]);             // quad-coalesced 16B
#pragma unroll
        for (int k = 0; k < 4; k++) {
            int s = __shfl_sync(0xffffffffu, a, qbase + k);
            float4 v = __ldg(&g_hs[(size_t)s * 4 + c]);
            acc.x += v.x; acc.y += v.y; acc.z += v.z; acc.w += v.w;
        }
    }
    for (; j < len; j++) {
        int s = __ldg(&row[j]);                 // broadcast within quad
        float4 v = __ldg(&g_hs[(size_t)s * 4 + c]);
        acc.x += v.x; acc.y += v.y; acc.z += v.z; acc.w += v.w;
    }

    // spill fold-in (normally g_spill_cnt == 0: one cached load, no loop)
    if (raw > SLOTS) {
        int m = g_spill_cnt;
        if (m > SPILLMAX) m = SPILLMAX;
        for (int i = 0; i < m; i++) {
            if (g_spill[2 * i + 1] == node) {
                int s = g_spill[2 * i];
                float4 v = __ldg(&g_hs[(size_t)s * 4 + c]);
                acc.x += v.x; acc.y += v.y; acc.z += v.z; acc.w += v.w;
            }
        }
    }

    g_agg[(size_t)node * 4 + c] = acc;          // 64B/quad, 512B/warp contiguous
}

// ---------------- y = relu(dinv*agg + b1) ; hs = (y @ W2) * dinv -------------
__global__ __launch_bounds__(256) void k_mid(const float* __restrict__ W2,
                                             const float* __restrict__ b1, int n) {
    __shared__ float sW[256];
    __shared__ float sb[16];
    int tid = threadIdx.x;
    sW[tid] = W2[tid];
    if (tid < 16) sb[tid] = b1[tid];
    __syncthreads();
    int i = blockIdx.x * 256 + tid;
    if (i >= n) return;

    float dv = g_dinv[i];
    float y[16];
#pragma unroll
    for (int c = 0; c < 4; c++) {
        float4 a = g_agg[(size_t)i * 4 + c];
        float v0 = a.x * dv + sb[c * 4 + 0];
        float v1 = a.y * dv + sb[c * 4 + 1];
        float v2 = a.z * dv + sb[c * 4 + 2];
        float v3 = a.w * dv + sb[c * 4 + 3];
        y[c * 4 + 0] = v0 > 0.0f ? v0 : 0.0f;
        y[c * 4 + 1] = v1 > 0.0f ? v1 : 0.0f;
        y[c * 4 + 2] = v2 > 0.0f ? v2 : 0.0f;
        y[c * 4 + 3] = v3 > 0.0f ? v3 : 0.0f;
    }
    float acc[16];
#pragma unroll
    for (int j = 0; j < 16; j++) acc[j] = 0.0f;
#pragma unroll
    for (int k = 0; k < 16; k++) {
        float yk = y[k];
#pragma unroll
        for (int j = 0; j < 16; j++) acc[j] += yk * sW[k * 16 + j];
    }
#pragma unroll
    for (int c = 0; c < 4; c++) {
        float4 o;
        o.x = acc[c * 4 + 0] * dv; o.y = acc[c * 4 + 1] * dv;
        o.z = acc[c * 4 + 2] * dv; o.w = acc[c * 4 + 3] * dv;
        g_hs[(size_t)i * 4 + c] = o;
    }
}

// ---------------- out = dinv*agg + b2 ----------------
__global__ __launch_bounds__(256) void k_final(const float* __restrict__ b2,
                                               float* __restrict__ out, int n) {
    __shared__ float sb[16];
    int tid = threadIdx.x;
    if (tid < 16) sb[tid] = b2[tid];
    __syncthreads();
    int i = blockIdx.x * 256 + tid;
    if (i >= n) return;

    float dv = g_dinv[i];
    float4* op = reinterpret_cast<float4*>(out) + (size_t)i * 4;
#pragma unroll
    for (int c = 0; c < 4; c++) {
        float4 a = g_agg[(size_t)i * 4 + c];
        float4 o;
        o.x = a.x * dv + sb[c * 4 + 0];
        o.y = a.y * dv + sb[c * 4 + 1];
        o.z = a.z * dv + sb[c * 4 + 2];
        o.w = a.w * dv + sb[c * 4 + 3];
        op[c] = o;
    }
}

extern "C" void kernel_launch(void* const* d_in, const int* in_sizes, int n_in,
                              void* d_out, int out_size) {
    const float* x  = (const float*)d_in[0];
    const int*   ei = (const int*)  d_in[1];
    const float* W1 = (const float*)d_in[2];
    const float* b1 = (const float*)d_in[3];
    const float* W2 = (const float*)d_in[4];
    const float* b2 = (const float*)d_in[5];
    float* out = (float*)d_out;

    int E = in_sizes[1] / 2;
    int n = in_sizes[0] / F;
    const int* src = ei;
    const int* dst = ei + E;

    int nb_n = (n + 255) / 256;
    int nb_e = (E + 255) / 256;
    int nb_a = (n + 63) / 64;      // 64 nodes per 256-thread block (4 lanes/node)

    k_init   <<<nb_n, 256>>>(n);
    k_bucket <<<nb_e, 256>>>(src, dst, E);
    k_pre1   <<<nb_n, 256>>>(x, W1, n);
    k_agg    <<<nb_a, 256>>>(n);
    k_mid    <<<nb_n, 256>>>(W2, b1, n);
    k_agg    <<<nb_a, 256>>>(n);
    k_final  <<<nb_n, 256>>>(b2, out, n);
}

// round 8
// speedup vs baseline: 1.1949x; 1.1320x over previous
#include <cuda_runtime.h>

// MeshGCN 2-layer GCN, N=100000, FEAT=16, E=3.2M.
// out_l[d] = dinv[d] * ( hs_l[d] + sum_{(s,d) in E} hs_l[s] ) + b_l
//   hs_l = (in_l @ W_l) * dinv,  dinv = rsqrt(deg_in + 1)
// Fixed-stride bucket adjacency (96 slots/node), one-pass build w/ degrees.
// Aggregation: 4 lanes/node, each lane owns one float4 column; unroll-8
// batches with 8 independent gathers in flight (MLP=8) and two accumulators
// to break the FADD chain. Latency-bound -> MLP is the lever.

#define NMAX 100000
#define F 16
#define SLOTS 96
#define SPILLMAX 8192

__device__ int    g_cnt[NMAX];
__device__ int    g_adj[NMAX * SLOTS];
__device__ int    g_spill_cnt;
__device__ int    g_spill[SPILLMAX * 2];
__device__ float  g_dinv[NMAX];
__device__ float4 g_hs [NMAX * 4];
__device__ float4 g_agg[NMAX * 4];

// ---------------- zero counters ----------------
__global__ __launch_bounds__(256) void k_init(int n) {
    int i = blockIdx.x * 256 + threadIdx.x;
    if (i < n) g_cnt[i] = 0;
    if (i == 0) g_spill_cnt = 0;
}

// ---------------- one-pass bucket build: degree + placement ----------------
__global__ __launch_bounds__(256) void k_bucket(const int* __restrict__ src,
                                                const int* __restrict__ dst, int E) {
    int e = blockIdx.x * 256 + threadIdx.x;
    if (e >= E) return;
    int s = src[e];
    int d = dst[e];
    int pos = atomicAdd(&g_cnt[d], 1);
    if (pos < SLOTS) {
        g_adj[(size_t)d * SLOTS + pos] = s;
    } else {
        int sp = atomicAdd(&g_spill_cnt, 1);
        if (sp < SPILLMAX) { g_spill[2 * sp] = s; g_spill[2 * sp + 1] = d; }
    }
}

// ---------------- dense: hs = (x @ W1) * dinv ----------------
__global__ __launch_bounds__(256) void k_pre1(const float* __restrict__ x,
                                              const float* __restrict__ W, int n) {
    __shared__ float sW[256];
    int tid = threadIdx.x;
    sW[tid] = W[tid];
    __syncthreads();
    int i = blockIdx.x * 256 + tid;
    if (i >= n) return;

    const float4* xp = reinterpret_cast<const float4*>(x) + (size_t)i * 4;
    float xr[16];
#pragma unroll
    for (int c = 0; c < 4; c++) {
        float4 t = xp[c];
        xr[c * 4 + 0] = t.x; xr[c * 4 + 1] = t.y;
        xr[c * 4 + 2] = t.z; xr[c * 4 + 3] = t.w;
    }
    float acc[16];
#pragma unroll
    for (int j = 0; j < 16; j++) acc[j] = 0.0f;
#pragma unroll
    for (int k = 0; k < 16; k++) {
        float xk = xr[k];
#pragma unroll
        for (int j = 0; j < 16; j++) acc[j] += xk * sW[k * 16 + j];
    }
    float dv = rsqrtf((float)(g_cnt[i] + 1));
    g_dinv[i] = dv;
#pragma unroll
    for (int c = 0; c < 4; c++) {
        float4 o;
        o.x = acc[c * 4 + 0] * dv; o.y = acc[c * 4 + 1] * dv;
        o.z = acc[c * 4 + 2] * dv; o.w = acc[c * 4 + 3] * dv;
        g_hs[(size_t)i * 4 + c] = o;
    }
}

// ---------------- aggregation: 4 lanes/node, unroll-8, MLP=8 ----------------
// agg[node] = hs[node] + sum_{s in bucket row} hs[s]
__global__ __launch_bounds__(256) void k_agg(int n) {
    int lane  = threadIdx.x & 31;
    int c     = lane & 3;                        // feature column (float4 slot)
    int qbase = lane & ~3;                       // first lane of this quad
    int node  = blockIdx.x * 64 + (threadIdx.x >> 2);
    if (node >= n) return;

    int raw = g_cnt[node];
    int len = raw < SLOTS ? raw : SLOTS;
    const int* row = &g_adj[(size_t)node * SLOTS];

    float4 acc0 = g_hs[(size_t)node * 4 + c];    // self-loop seed
    float4 acc1 = make_float4(0.f, 0.f, 0.f, 0.f);

    int j = 0;
    for (; j + 8 <= len; j += 8) {
        int a0 = __ldg(&row[j + c]);             // quad-coalesced
        int a1 = __ldg(&row[j + 4 + c]);
        float4 v0, v1, v2, v3, v4, v5, v6, v7;
        {   // issue all 8 gathers before any accumulation (independent regs)
            int s;
            s = __shfl_sync(0xffffffffu, a0, qbase + 0); v0 = __ldg(&g_hs[(size_t)s * 4 + c]);
            s = __shfl_sync(0xffffffffu, a0, qbase + 1); v1 = __ldg(&g_hs[(size_t)s * 4 + c]);
            s = __shfl_sync(0xffffffffu, a0, qbase + 2); v2 = __ldg(&g_hs[(size_t)s * 4 + c]);
            s = __shfl_sync(0xffffffffu, a0, qbase + 3); v3 = __ldg(&g_hs[(size_t)s * 4 + c]);
            s = __shfl_sync(0xffffffffu, a1, qbase + 0); v4 = __ldg(&g_hs[(size_t)s * 4 + c]);
            s = __shfl_sync(0xffffffffu, a1, qbase + 1); v5 = __ldg(&g_hs[(size_t)s * 4 + c]);
            s = __shfl_sync(0xffffffffu, a1, qbase + 2); v6 = __ldg(&g_hs[(size_t)s * 4 + c]);
            s = __shfl_sync(0xffffffffu, a1, qbase + 3); v7 = __ldg(&g_hs[(size_t)s * 4 + c]);
        }
        acc0.x += v0.x; acc0.y += v0.y; acc0.z += v0.z; acc0.w += v0.w;
        acc1.x += v1.x; acc1.y += v1.y; acc1.z += v1.z; acc1.w += v1.w;
        acc0.x += v2.x; acc0.y += v2.y; acc0.z += v2.z; acc0.w += v2.w;
        acc1.x += v3.x; acc1.y += v3.y; acc1.z += v3.z; acc1.w += v3.w;
        acc0.x += v4.x; acc0.y += v4.y; acc0.z += v4.z; acc0.w += v4.w;
        acc1.x += v5.x; acc1.y += v5.y; acc1.z += v5.z; acc1.w += v5.w;
        acc0.x += v6.x; acc0.y += v6.y; acc0.z += v6.z; acc0.w += v6.w;
        acc1.x += v7.x; acc1.y += v7.y; acc1.z += v7.z; acc1.w += v7.w;
    }
    if (j + 4 <= len) {
        int a = __ldg(&row[j + c]);
        float4 v0, v1, v2, v3;
        int s;
        s = __shfl_sync(0xffffffffu, a, qbase + 0); v0 = __ldg(&g_hs[(size_t)s * 4 + c]);
        s = __shfl_sync(0xffffffffu, a, qbase + 1); v1 = __ldg(&g_hs[(size_t)s * 4 + c]);
        s = __shfl_sync(0xffffffffu, a, qbase + 2); v2 = __ldg(&g_hs[(size_t)s * 4 + c]);
        s = __shfl_sync(0xffffffffu, a, qbase + 3); v3 = __ldg(&g_hs[(size_t)s * 4 + c]);
        acc0.x += v0.x; acc0.y += v0.y; acc0.z += v0.z; acc0.w += v0.w;
        acc1.x += v1.x; acc1.y += v1.y; acc1.z += v1.z; acc1.w += v1.w;
        acc0.x += v2.x; acc0.y += v2.y; acc0.z += v2.z; acc0.w += v2.w;
        acc1.x += v3.x; acc1.y += v3.y; acc1.z += v3.z; acc1.w += v3.w;
        j += 4;
    }
    for (; j < len; j++) {
        int s = __ldg(&row[j]);
        float4 v = __ldg(&g_hs[(size_t)s * 4 + c]);
        acc0.x += v.x; acc0.y += v.y; acc0.z += v.z; acc0.w += v.w;
    }

    // spill fold-in (normally dead: raw <= SLOTS for every node)
    if (raw > SLOTS) {
        int m = g_spill_cnt;
        if (m > SPILLMAX) m = SPILLMAX;
        for (int i = 0; i < m; i++) {
            if (g_spill[2 * i + 1] == node) {
                int s = g_spill[2 * i];
                float4 v = __ldg(&g_hs[(size_t)s * 4 + c]);
                acc0.x += v.x; acc0.y += v.y; acc0.z += v.z; acc0.w += v.w;
            }
        }
    }

    float4 o;
    o.x = acc0.x + acc1.x; o.y = acc0.y + acc1.y;
    o.z = acc0.z + acc1.z; o.w = acc0.w + acc1.w;
    g_agg[(size_t)node * 4 + c] = o;             // 512B/warp contiguous
}

// ---------------- y = relu(dinv*agg + b1) ; hs = (y @ W2) * dinv -------------
__global__ __launch_bounds__(256) void k_mid(const float* __restrict__ W2,
                                             const float* __restrict__ b1, int n) {
    __shared__ float sW[256];
    __shared__ float sb[16];
    int tid = threadIdx.x;
    sW[tid] = W2[tid];
    if (tid < 16) sb[tid] = b1[tid];
    __syncthreads();
    int i = blockIdx.x * 256 + tid;
    if (i >= n) return;

    float dv = g_dinv[i];
    float y[16];
#pragma unroll
    for (int c = 0; c < 4; c++) {
        float4 a = g_agg[(size_t)i * 4 + c];
        float v0 = a.x * dv + sb[c * 4 + 0];
        float v1 = a.y * dv + sb[c * 4 + 1];
        float v2 = a.z * dv + sb[c * 4 + 2];
        float v3 = a.w * dv + sb[c * 4 + 3];
        y[c * 4 + 0] = v0 > 0.0f ? v0 : 0.0f;
        y[c * 4 + 1] = v1 > 0.0f ? v1 : 0.0f;
        y[c * 4 + 2] = v2 > 0.0f ? v2 : 0.0f;
        y[c * 4 + 3] = v3 > 0.0f ? v3 : 0.0f;
    }
    float acc[16];
#pragma unroll
    for (int j = 0; j < 16; j++) acc[j] = 0.0f;
#pragma unroll
    for (int k = 0; k < 16; k++) {
        float yk = y[k];
#pragma unroll
        for (int j = 0; j < 16; j++) acc[j] += yk * sW[k * 16 + j];
    }
#pragma unroll
    for (int c = 0; c < 4; c++) {
        float4 o;
        o.x = acc[c * 4 + 0] * dv; o.y = acc[c * 4 + 1] * dv;
        o.z = acc[c * 4 + 2] * dv; o.w = acc[c * 4 + 3] * dv;
        g_hs[(size_t)i * 4 + c] = o;
    }
}

// ---------------- out = dinv*agg + b2 ----------------
__global__ __launch_bounds__(256) void k_final(const float* __restrict__ b2,
                                               float* __restrict__ out, int n) {
    __shared__ float sb[16];
    int tid = threadIdx.x;
    if (tid < 16) sb[tid] = b2[tid];
    __syncthreads();
    int i = blockIdx.x * 256 + tid;
    if (i >= n) return;

    float dv = g_dinv[i];
    float4* op = reinterpret_cast<float4*>(out) + (size_t)i * 4;
#pragma unroll
    for (int c = 0; c < 4; c++) {
        float4 a = g_agg[(size_t)i * 4 + c];
        float4 o;
        o.x = a.x * dv + sb[c * 4 + 0];
        o.y = a.y * dv + sb[c * 4 + 1];
        o.z = a.z * dv + sb[c * 4 + 2];
        o.w = a.w * dv + sb[c * 4 + 3];
        op[c] = o;
    }
}

extern "C" void kernel_launch(void* const* d_in, const int* in_sizes, int n_in,
                              void* d_out, int out_size) {
    const float* x  = (const float*)d_in[0];
    const int*   ei = (const int*)  d_in[1];
    const float* W1 = (const float*)d_in[2];
    const float* b1 = (const float*)d_in[3];
    const float* W2 = (const float*)d_in[4];
    const float* b2 = (const float*)d_in[5];
    float* out = (float*)d_out;

    int E = in_sizes[1] / 2;
    int n = in_sizes[0] / F;
    const int* src = ei;
    const int* dst = ei + E;

    int nb_n = (n + 255) / 256;
    int nb_e = (E + 255) / 256;
    int nb_a = (n + 63) / 64;      // 64 nodes per 256-thread block

    k_init   <<<nb_n, 256>>>(n);
    k_bucket <<<nb_e, 256>>>(src, dst, E);
    k_pre1   <<<nb_n, 256>>>(x, W1, n);
    k_agg    <<<nb_a, 256>>>(n);
    k_mid    <<<nb_n, 256>>>(W2, b1, n);
    k_agg    <<<nb_a, 256>>>(n);
    k_final  <<<nb_n, 256>>>(b2, out, n);
}

// round 9
// speedup vs baseline: 1.3652x; 1.1425x over previous
#include <cuda_runtime.h>

// MeshGCN 2-layer GCN, N=100000, FEAT=16, E=3.2M.
// out_l[d] = dinv[d] * ( hs_l[d] + sum_{(s,d) in E} hs_l[s] ) + b_l
//   hs_l = (in_l @ W_l) * dinv,  dinv = rsqrt(deg_in + 1)
// Bucket adjacency (96 slots/node), one-pass build. Aggregation: 8 lanes per
// node, each lane owns one float2 feature column (no reduction tail), unroll-8
// neighbor batches with prefetched adjacency -> MLP=8 per lane at ~36 regs so
// occupancy stays high. Latency-bound gather: maximize warps x loads-in-flight.

#define NMAX 100000
#define F 16
#define SLOTS 96
#define SPILLMAX 8192

__device__ int    g_cnt[NMAX];
__device__ int    g_adj[NMAX * SLOTS];
__device__ int    g_spill_cnt;
__device__ int    g_spill[SPILLMAX * 2];
__device__ float  g_dinv[NMAX];
__device__ float4 g_hs [NMAX * 4];
__device__ float4 g_agg[NMAX * 4];

// ---------------- zero counters ----------------
__global__ __launch_bounds__(256) void k_init(int n) {
    int i = blockIdx.x * 256 + threadIdx.x;
    if (i < n) g_cnt[i] = 0;
    if (i == 0) g_spill_cnt = 0;
}

// ---------------- one-pass bucket build: degree + placement (2 edges/thread) --
__global__ __launch_bounds__(256) void k_bucket(const int* __restrict__ src,
                                                const int* __restrict__ dst, int E) {
    int t = blockIdx.x * 256 + threadIdx.x;
    int e = t * 2;
    if (e + 1 < E) {
        int2 s2 = *reinterpret_cast<const int2*>(src + e);
        int2 d2 = *reinterpret_cast<const int2*>(dst + e);
        int p0 = atomicAdd(&g_cnt[d2.x], 1);
        int p1 = atomicAdd(&g_cnt[d2.y], 1);
        if (p0 < SLOTS) g_adj[(size_t)d2.x * SLOTS + p0] = s2.x;
        else { int sp = atomicAdd(&g_spill_cnt, 1);
               if (sp < SPILLMAX) { g_spill[2*sp] = s2.x; g_spill[2*sp+1] = d2.x; } }
        if (p1 < SLOTS) g_adj[(size_t)d2.y * SLOTS + p1] = s2.y;
        else { int sp = atomicAdd(&g_spill_cnt, 1);
               if (sp < SPILLMAX) { g_spill[2*sp] = s2.y; g_spill[2*sp+1] = d2.y; } }
    } else if (e < E) {
        int s = src[e], d = dst[e];
        int p = atomicAdd(&g_cnt[d], 1);
        if (p < SLOTS) g_adj[(size_t)d * SLOTS + p] = s;
        else { int sp = atomicAdd(&g_spill_cnt, 1);
               if (sp < SPILLMAX) { g_spill[2*sp] = s; g_spill[2*sp+1] = d; } }
    }
}

// ---------------- dense: hs = (x @ W1) * dinv ----------------
__global__ __launch_bounds__(256) void k_pre1(const float* __restrict__ x,
                                              const float* __restrict__ W, int n) {
    __shared__ float sW[256];
    int tid = threadIdx.x;
    sW[tid] = W[tid];
    __syncthreads();
    int i = blockIdx.x * 256 + tid;
    if (i >= n) return;

    const float4* xp = reinterpret_cast<const float4*>(x) + (size_t)i * 4;
    float xr[16];
#pragma unroll
    for (int c = 0; c < 4; c++) {
        float4 t = xp[c];
        xr[c * 4 + 0] = t.x; xr[c * 4 + 1] = t.y;
        xr[c * 4 + 2] = t.z; xr[c * 4 + 3] = t.w;
    }
    float acc[16];
#pragma unroll
    for (int j = 0; j < 16; j++) acc[j] = 0.0f;
#pragma unroll
    for (int k = 0; k < 16; k++) {
        float xk = xr[k];
#pragma unroll
        for (int j = 0; j < 16; j++) acc[j] += xk * sW[k * 16 + j];
    }
    float dv = rsqrtf((float)(g_cnt[i] + 1));
    g_dinv[i] = dv;
#pragma unroll
    for (int c = 0; c < 4; c++) {
        float4 o;
        o.x = acc[c * 4 + 0] * dv; o.y = acc[c * 4 + 1] * dv;
        o.z = acc[c * 4 + 2] * dv; o.w = acc[c * 4 + 3] * dv;
        g_hs[(size_t)i * 4 + c] = o;
    }
}

// ---------------- aggregation: 8 lanes/node, float2 columns, MLP=8 ----------
// agg[node] = hs[node] + sum_{s in bucket row} hs[s]
__global__ __launch_bounds__(256) void k_agg(int n) {
    int lane  = threadIdx.x & 31;
    int o     = lane & 7;                        // float2 column (0..7)
    int obase = lane & ~7;                       // first lane of this octet
    int node  = blockIdx.x * 32 + (threadIdx.x >> 3);   // 32 nodes per block
    if (node >= n) return;

    int raw = g_cnt[node];
    int len = raw < SLOTS ? raw : SLOTS;
    const int* row = &g_adj[(size_t)node * SLOTS];
    const float2* hs2 = reinterpret_cast<const float2*>(g_hs);

    float2 acc0 = hs2[(size_t)node * 8 + o];     // self-loop seed
    float2 acc1 = make_float2(0.f, 0.f);

    int a = __ldg(&row[o]);                      // prefetch batch 0 (safe: SLOTS>=8)
    int j = 0;
    for (; j + 8 <= len; j += 8) {
        int a_cur = a;
        if (j + 16 <= len) a = __ldg(&row[j + 8 + o]);   // prefetch next batch
        int s;
        float2 v0, v1, v2, v3, v4, v5, v6, v7;
        s = __shfl_sync(0xffffffffu, a_cur, obase + 0); v0 = __ldg(&hs2[(size_t)s * 8 + o]);
        s = __shfl_sync(0xffffffffu, a_cur, obase + 1); v1 = __ldg(&hs2[(size_t)s * 8 + o]);
        s = __shfl_sync(0xffffffffu, a_cur, obase + 2); v2 = __ldg(&hs2[(size_t)s * 8 + o]);
        s = __shfl_sync(0xffffffffu, a_cur, obase + 3); v3 = __ldg(&hs2[(size_t)s * 8 + o]);
        s = __shfl_sync(0xffffffffu, a_cur, obase + 4); v4 = __ldg(&hs2[(size_t)s * 8 + o]);
        s = __shfl_sync(0xffffffffu, a_cur, obase + 5); v5 = __ldg(&hs2[(size_t)s * 8 + o]);
        s = __shfl_sync(0xffffffffu, a_cur, obase + 6); v6 = __ldg(&hs2[(size_t)s * 8 + o]);
        s = __shfl_sync(0xffffffffu, a_cur, obase + 7); v7 = __ldg(&hs2[(size_t)s * 8 + o]);
        acc0.x += v0.x; acc0.y += v0.y;
        acc1.x += v1.x; acc1.y += v1.y;
        acc0.x += v2.x; acc0.y += v2.y;
        acc1.x += v3.x; acc1.y += v3.y;
        acc0.x += v4.x; acc0.y += v4.y;
        acc1.x += v5.x; acc1.y += v5.y;
        acc0.x += v6.x; acc0.y += v6.y;
        acc1.x += v7.x; acc1.y += v7.y;
    }
    for (; j < len; j++) {                       // tail: octet-broadcast load
        int s = __ldg(&row[j]);
        float2 v = __ldg(&hs2[(size_t)s * 8 + o]);
        acc0.x += v.x; acc0.y += v.y;
    }

    // spill fold-in (normally dead)
    if (raw > SLOTS) {
        int m = g_spill_cnt;
        if (m > SPILLMAX) m = SPILLMAX;
        for (int i = 0; i < m; i++) {
            if (g_spill[2 * i + 1] == node) {
                int s = g_spill[2 * i];
                float2 v = __ldg(&hs2[(size_t)s * 8 + o]);
                acc0.x += v.x; acc0.y += v.y;
            }
        }
    }

    float2* agg2 = reinterpret_cast<float2*>(g_agg);
    agg2[(size_t)node * 8 + o] = make_float2(acc0.x + acc1.x, acc0.y + acc1.y);
}

// ---------------- y = relu(dinv*agg + b1) ; hs = (y @ W2) * dinv -------------
__global__ __launch_bounds__(256) void k_mid(const float* __restrict__ W2,
                                             const float* __restrict__ b1, int n) {
    __shared__ float sW[256];
    __shared__ float sb[16];
    int tid = threadIdx.x;
    sW[tid] = W2[tid];
    if (tid < 16) sb[tid] = b1[tid];
    __syncthreads();
    int i = blockIdx.x * 256 + tid;
    if (i >= n) return;

    float dv = g_dinv[i];
    float y[16];
#pragma unroll
    for (int c = 0; c < 4; c++) {
        float4 a = g_agg[(size_t)i * 4 + c];
        float v0 = a.x * dv + sb[c * 4 + 0];
        float v1 = a.y * dv + sb[c * 4 + 1];
        float v2 = a.z * dv + sb[c * 4 + 2];
        float v3 = a.w * dv + sb[c * 4 + 3];
        y[c * 4 + 0] = v0 > 0.0f ? v0 : 0.0f;
        y[c * 4 + 1] = v1 > 0.0f ? v1 : 0.0f;
        y[c * 4 + 2] = v2 > 0.0f ? v2 : 0.0f;
        y[c * 4 + 3] = v3 > 0.0f ? v3 : 0.0f;
    }
    float acc[16];
#pragma unroll
    for (int j = 0; j < 16; j++) acc[j] = 0.0f;
#pragma unroll
    for (int k = 0; k < 16; k++) {
        float yk = y[k];
#pragma unroll
        for (int j = 0; j < 16; j++) acc[j] += yk * sW[k * 16 + j];
    }
#pragma unroll
    for (int c = 0; c < 4; c++) {
        float4 o;
        o.x = acc[c * 4 + 0] * dv; o.y = acc[c * 4 + 1] * dv;
        o.z = acc[c * 4 + 2] * dv; o.w = acc[c * 4 + 3] * dv;
        g_hs[(size_t)i * 4 + c] = o;
    }
}

// ---------------- out = dinv*agg + b2 ----------------
__global__ __launch_bounds__(256) void k_final(const float* __restrict__ b2,
                                               float* __restrict__ out, int n) {
    __shared__ float sb[16];
    int tid = threadIdx.x;
    if (tid < 16) sb[tid] = b2[tid];
    __syncthreads();
    int i = blockIdx.x * 256 + tid;
    if (i >= n) return;

    float dv = g_dinv[i];
    float4* op = reinterpret_cast<float4*>(out) + (size_t)i * 4;
#pragma unroll
    for (int c = 0; c < 4; c++) {
        float4 a = g_agg[(size_t)i * 4 + c];
        float4 o;
        o.x = a.x * dv + sb[c * 4 + 0];
        o.y = a.y * dv + sb[c * 4 + 1];
        o.z = a.z * dv + sb[c * 4 + 2];
        o.w = a.w * dv + sb[c * 4 + 3];
        op[c] = o;
    }
}

extern "C" void kernel_launch(void* const* d_in, const int* in_sizes, int n_in,
                              void* d_out, int out_size) {
    const float* x  = (const float*)d_in[0];
    const int*   ei = (const int*)  d_in[1];
    const float* W1 = (const float*)d_in[2];
    const float* b1 = (const float*)d_in[3];
    const float* W2 = (const float*)d_in[4];
    const float* b2 = (const float*)d_in[5];
    float* out = (float*)d_out;

    int E = in_sizes[1] / 2;
    int n = in_sizes[0] / F;
    const int* src = ei;
    const int* dst = ei + E;

    int nb_n = (n + 255) / 256;
    int nb_e = (E / 2 + 255) / 256;   // 2 edges per thread
    int nb_a = (n + 31) / 32;         // 32 nodes per 256-thread block (8 lanes/node)

    k_init   <<<nb_n, 256>>>(n);
    k_bucket <<<nb_e, 256>>>(src, dst, E);
    k_pre1   <<<nb_n, 256>>>(x, W1, n);
    k_agg    <<<nb_a, 256>>>(n);
    k_mid    <<<nb_n, 256>>>(W2, b1, n);
    k_agg    <<<nb_a, 256>>>(n);
    k_final  <<<nb_n, 256>>>(b2, out, n);
}